// round 6
// baseline (speedup 1.0000x reference)
#include <cuda_runtime.h>
#include <math.h>

#define BB 16
#define TT 4096
#define DD 1024
#define CCLS 1000
#define KK 4
#define TOPM 8
#define TEMPR (1.0f/0.07f)
#define EPSV 1e-6f

#define TOK_PER_WARP 8
#define W_BLOCKS (CCLS * KK)                         // 4000
#define C_BLOCKS ((BB * TT) / (8 * TOK_PER_WARP))    // 1024

// scratch (allocation-free rule: __device__ globals)
__device__ float g_u[KK * DD];       // unit peel directions
__device__ float g_gram[KK * KK];    // u_j . u_k (only j<k entries used)
__device__ float g_w[KK * CCLS];     // W_k @ u_k
__device__ float g_C[KK * BB * TT];  // coefficient fields c_k[b,t]
__device__ float g_s[BB * KK];       // 0.5*(hard+soft) scalars
__device__ int   g_cnt = 0;          // stats completion counter (self-resetting)

// ---------------- Kernel A: u_k and Gram, shuffle-parallel -----------------
__global__ void prep_kernel(const float* __restrict__ v,
                            const float* __restrict__ m) {
    int tid = threadIdx.x;            // 1024 threads, tid == d
    int wid = tid >> 5, lane = tid & 31;
    float val[KK], ss[KK];
#pragma unroll
    for (int k = 0; k < KK; k++) {
        float mv = m[k * DD + tid];
        float sig = 1.0f / (1.0f + expf(-mv));
        val[k] = v[k * DD + tid] * sig;
        ss[k] = val[k] * val[k];
    }
#pragma unroll
    for (int off = 16; off; off >>= 1)
#pragma unroll
        for (int k = 0; k < KK; k++)
            ss[k] += __shfl_xor_sync(0xFFFFFFFFu, ss[k], off);

    __shared__ float sred[32][KK];
    __shared__ float sinv[KK];
    if (lane == 0)
#pragma unroll
        for (int k = 0; k < KK; k++) sred[wid][k] = ss[k];
    __syncthreads();
    if (tid < 32) {
        float t[KK];
#pragma unroll
        for (int k = 0; k < KK; k++) t[k] = sred[tid][k];
#pragma unroll
        for (int off = 16; off; off >>= 1)
#pragma unroll
            for (int k = 0; k < KK; k++)
                t[k] += __shfl_xor_sync(0xFFFFFFFFu, t[k], off);
        if (tid == 0)
#pragma unroll
            for (int k = 0; k < KK; k++) sinv[k] = 1.0f / (sqrtf(t[k]) + EPSV);
    }
    __syncthreads();
    float un[KK];
#pragma unroll
    for (int k = 0; k < KK; k++) {
        un[k] = val[k] * sinv[k];
        g_u[k * DD + tid] = un[k];
    }
    // Gram: 6 upper-triangle pairs in parallel
    float pp[6] = {un[0]*un[1], un[0]*un[2], un[0]*un[3],
                   un[1]*un[2], un[1]*un[3], un[2]*un[3]};
#pragma unroll
    for (int off = 16; off; off >>= 1)
#pragma unroll
        for (int p = 0; p < 6; p++)
            pp[p] += __shfl_xor_sync(0xFFFFFFFFu, pp[p], off);
    __shared__ float sred6[32][6];
    if (lane == 0)
#pragma unroll
        for (int p = 0; p < 6; p++) sred6[wid][p] = pp[p];
    __syncthreads();
    if (tid < 32) {
        float t[6];
#pragma unroll
        for (int p = 0; p < 6; p++) t[p] = sred6[tid][p];
#pragma unroll
        for (int off = 16; off; off >>= 1)
#pragma unroll
            for (int p = 0; p < 6; p++)
                t[p] += __shfl_xor_sync(0xFFFFFFFFu, t[p], off);
        if (tid == 0) {
            g_gram[0 * KK + 1] = t[0];
            g_gram[0 * KK + 2] = t[1];
            g_gram[0 * KK + 3] = t[2];
            g_gram[1 * KK + 2] = t[3];
            g_gram[1 * KK + 3] = t[4];
            g_gram[2 * KK + 3] = t[5];
        }
    }
}

// ---------------- Fused kernel: w projection + coefficient pass ------------
// Blocks [0, W_BLOCKS):          w_k[c] = cls_W[k,c,:] . u_k
// Blocks [W_BLOCKS, +C_BLOCKS):  one pass over E -> c_k (8 tokens/warp)
// Streaming loads (__ldcs) on E and W: read-once data, keep L2 for g_C.
__global__ void __launch_bounds__(256)
fused_kernel(const float* __restrict__ E,
             const float* __restrict__ W,
             const float* __restrict__ beta) {
    __shared__ float su[KK * DD];    // 16 KB: the 4 u vectors (coeff part)
    __shared__ float sg[KK * KK];
    __shared__ float sb[KK];

    int tid = threadIdx.x;           // 256
    int wid = tid >> 5, lane = tid & 31;

    if (blockIdx.x < W_BLOCKS) {
        // ---- w part: one block per (k, c) ----
        int bx = blockIdx.x;
        int k = bx / CCLS;
        int c = bx - k * CCLS;
        const float4* wr = (const float4*)(W + ((size_t)k * CCLS + c) * DD);
        const float4* u4g = (const float4*)(g_u + k * DD);
        float4 w = __ldcs(wr + tid);
        float4 u = u4g[tid];
        float acc = w.x * u.x + w.y * u.y + w.z * u.z + w.w * u.w;
#pragma unroll
        for (int off = 16; off; off >>= 1)
            acc += __shfl_xor_sync(0xFFFFFFFFu, acc, off);
        __shared__ float sd[8];
        if (lane == 0) sd[wid] = acc;
        __syncthreads();
        if (tid == 0) {
            float s = sd[0];
#pragma unroll
            for (int i = 1; i < 8; i++) s += sd[i];
            g_w[k * CCLS + c] = s;
        }
        return;
    }

    // ---- coeff part: warp handles TOK_PER_WARP tokens ----
    int cb = blockIdx.x - W_BLOCKS;
    for (int i = tid; i < KK * DD; i += 256) su[i] = g_u[i];
    if (tid < KK * KK) sg[tid] = g_gram[tid];
    if (tid < KK) sb[tid] = beta[tid];
    __syncthreads();

    int tok0 = (cb * 8 + wid) * TOK_PER_WARP;
    const float4* u4 = (const float4*)su;
    const float4* e4 = (const float4*)(E + (size_t)tok0 * DD);

    float acc[TOK_PER_WARP][KK];
#pragma unroll
    for (int j = 0; j < TOK_PER_WARP; j++)
#pragma unroll
        for (int k = 0; k < KK; k++) acc[j][k] = 0.f;

#pragma unroll
    for (int i = 0; i < 8; i++) {
        int idx = i * 32 + lane;
        float4 ua = u4[idx];
        float4 ub = u4[256 + idx];
        float4 uc = u4[512 + idx];
        float4 ud = u4[768 + idx];
#pragma unroll
        for (int j = 0; j < TOK_PER_WARP; j++) {
            float4 e = __ldcs(e4 + (size_t)j * 256 + idx);
            acc[j][0] += e.x*ua.x + e.y*ua.y + e.z*ua.z + e.w*ua.w;
            acc[j][1] += e.x*ub.x + e.y*ub.y + e.z*ub.z + e.w*ub.w;
            acc[j][2] += e.x*uc.x + e.y*uc.y + e.z*uc.z + e.w*uc.w;
            acc[j][3] += e.x*ud.x + e.y*ud.y + e.z*ud.z + e.w*ud.w;
        }
    }
#pragma unroll
    for (int off = 16; off; off >>= 1)
#pragma unroll
        for (int j = 0; j < TOK_PER_WARP; j++)
#pragma unroll
            for (int k = 0; k < KK; k++)
                acc[j][k] += __shfl_down_sync(0xFFFFFFFFu, acc[j][k], off);

    if (lane == 0) {
#pragma unroll
        for (int j = 0; j < TOK_PER_WARP; j++) {
            int token = tok0 + j;
            float c0 = acc[j][0];
            float c1 = acc[j][1] - sb[0]*c0*sg[0*KK+1];
            float c2 = acc[j][2] - sb[0]*c0*sg[0*KK+2] - sb[1]*c1*sg[1*KK+2];
            float c3 = acc[j][3] - sb[0]*c0*sg[0*KK+3] - sb[1]*c1*sg[1*KK+3]
                                 - sb[2]*c2*sg[2*KK+3];
            g_C[0 * BB * TT + token] = c0;
            g_C[1 * BB * TT + token] = c1;
            g_C[2 * BB * TT + token] = c2;
            g_C[3 * BB * TT + token] = c3;
        }
    }
}

// ---------------- Kernel D: stats per (b,k) + fused output -----------------
// 512 threads; row in registers; warp-local top-8 then single-warp merge.
// The LAST finishing block also computes out[b,c] (fused, saves a launch),
// then resets the counter so graph replays stay deterministic.
__global__ void stats_kernel(const float* __restrict__ clsb,
                             const float* __restrict__ alpha,
                             float* __restrict__ out) {
    int b = blockIdx.x;
    int k = blockIdx.y;
    int tid = threadIdx.x;           // 512
    int wid = tid >> 5, lane = tid & 31;
    const float4* src = (const float4*)(g_C + ((size_t)k * BB + b) * TT);
    float4 p = src[tid];
    float4 q = src[tid + 512];
    float r[8] = {p.x, p.y, p.z, p.w, q.x, q.y, q.z, q.w};

    __shared__ float smax[16];
    __shared__ float sse[16];
    __shared__ float ssce[16];
    __shared__ float cand[16 * TOPM];   // per-warp top-8 candidates
    __shared__ int s_last;

    // block max (one barrier)
    float mx = r[0];
#pragma unroll
    for (int s = 1; s < 8; s++) mx = fmaxf(mx, r[s]);
#pragma unroll
    for (int off = 16; off; off >>= 1)
        mx = fmaxf(mx, __shfl_xor_sync(0xFFFFFFFFu, mx, off));
    if (lane == 0) smax[wid] = mx;
    __syncthreads();
    mx = smax[0];
#pragma unroll
    for (int w = 1; w < 16; w++) mx = fmaxf(mx, smax[w]);

    // exp sums (warp partials -> smem; merged by warp 0 later)
    float se = 0.f, sce = 0.f;
#pragma unroll
    for (int s = 0; s < 8; s++) {
        float e = __expf((r[s] - mx) * TEMPR);
        se += e;
        sce += r[s] * e;
    }
#pragma unroll
    for (int off = 16; off; off >>= 1) {
        se  += __shfl_xor_sync(0xFFFFFFFFu, se, off);
        sce += __shfl_xor_sync(0xFFFFFFFFu, sce, off);
    }
    if (lane == 0) { sse[wid] = se; ssce[wid] = sce; }

    // warp-local top-8 (no barriers): 8 rounds of warp argmax with exclusion
    unsigned excl = 0;
#pragma unroll
    for (int rr = 0; rr < TOPM; rr++) {
        float lm = -INFINITY;
        int ls = 0;
#pragma unroll
        for (int s = 0; s < 8; s++) {
            bool ok = !((excl >> s) & 1u);
            if (ok && r[s] > lm) { lm = r[s]; ls = s; }
        }
        int li = (lane << 3) | ls;
#pragma unroll
        for (int off = 16; off; off >>= 1) {
            float ov = __shfl_xor_sync(0xFFFFFFFFu, lm, off);
            int   oi = __shfl_xor_sync(0xFFFFFFFFu, li, off);
            if (ov > lm) { lm = ov; li = oi; }
        }
        if (lane == 0) cand[wid * TOPM + rr] = lm;
        if ((li >> 3) == lane) excl |= 1u << (li & 7);
    }
    __syncthreads();

    // warp 0 merges 128 candidates -> block top-8 and writes result
    if (wid == 0) {
        float c4[4];
#pragma unroll
        for (int i = 0; i < 4; i++) c4[i] = cand[lane * 4 + i];
        unsigned ex2 = 0;
        float hard = 0.f;
#pragma unroll
        for (int rr = 0; rr < TOPM; rr++) {
            float lm = -INFINITY;
            int ls = 0;
#pragma unroll
            for (int s = 0; s < 4; s++) {
                bool ok = !((ex2 >> s) & 1u);
                if (ok && c4[s] > lm) { lm = c4[s]; ls = s; }
            }
            int li = (lane << 2) | ls;
#pragma unroll
            for (int off = 16; off; off >>= 1) {
                float ov = __shfl_xor_sync(0xFFFFFFFFu, lm, off);
                int   oi = __shfl_xor_sync(0xFFFFFFFFu, li, off);
                if (ov > lm) { lm = ov; li = oi; }
            }
            hard += lm;
            if ((li >> 2) == lane) ex2 |= 1u << (li & 3);
        }
        if (lane == 0) {
            float se_t = 0.f, sce_t = 0.f;
#pragma unroll
            for (int w = 0; w < 16; w++) { se_t += sse[w]; sce_t += ssce[w]; }
            g_s[b * KK + k] = 0.5f * (hard + sce_t / se_t);
            __threadfence();
            int prev = atomicAdd(&g_cnt, 1);
            s_last = (prev == BB * KK - 1) ? 1 : 0;
        }
    }
    __syncthreads();

    // last block computes the output (all g_s now visible)
    if (s_last) {
        __threadfence();
        __shared__ float sal[KK], ssv[BB * KK];
        if (tid < KK) sal[tid] = alpha[tid];
        if (tid < BB * KK) ssv[tid] = g_s[tid];
        __syncthreads();
        for (int i = tid; i < BB * CCLS; i += 512) {
            int bb = i / CCLS;
            int c = i - bb * CCLS;
            float acc2 = 0.f;
#pragma unroll
            for (int kk2 = 0; kk2 < KK; kk2++) {
                acc2 += sal[kk2] * (ssv[bb * KK + kk2] * g_w[kk2 * CCLS + c]
                                    + clsb[kk2 * CCLS + c]);
            }
            out[i] = acc2;
        }
        // reset counter for deterministic graph replays
        if (tid == 0) g_cnt = 0;
    }
}

extern "C" void kernel_launch(void* const* d_in, const int* in_sizes, int n_in,
                              void* d_out, int out_size) {
    const float* E      = (const float*)d_in[0];  // (B,T,D)
    const float* v      = (const float*)d_in[1];  // (K,D)
    const float* mlog   = (const float*)d_in[2];  // (K,D)
    const float* clsW   = (const float*)d_in[3];  // (K,C,D)
    const float* clsb   = (const float*)d_in[4];  // (K,C)
    const float* beta   = (const float*)d_in[5];  // (K,)
    const float* alpha  = (const float*)d_in[6];  // (K,)
    float* out = (float*)d_out;                   // (B,C)

    prep_kernel<<<1, 1024>>>(v, mlog);
    fused_kernel<<<W_BLOCKS + C_BLOCKS, 256>>>(E, clsW, beta);
    dim3 sg(BB, KK);
    stats_kernel<<<sg, 512>>>(clsb, alpha, out);
}

// round 7
// speedup vs baseline: 1.1056x; 1.1056x over previous
#include <cuda_runtime.h>
#include <math.h>

#define BB 16
#define TT 4096
#define DD 1024
#define CCLS 1000
#define KK 4
#define TOPM 8
#define TEMPR (1.0f/0.07f)
#define EPSV 1e-6f

#define W_BLOCKS (CCLS * KK)           // 4000
#define C_BLOCKS ((BB * TT) / 32)      // 2048 (4 tokens per warp, 8 warps)

// scratch (allocation-free rule: __device__ globals)
__device__ float g_u[KK * DD];       // unit peel directions
__device__ float g_gram[KK * KK];    // u_j . u_k (only j<k entries used)
__device__ float g_w[KK * CCLS];     // W_k @ u_k
__device__ float g_C[KK * BB * TT];  // coefficient fields c_k[b,t]
__device__ float g_s[BB * KK];       // 0.5*(hard+soft) scalars
__device__ int   g_cnt = 0;          // stats completion counter (self-resetting)

// ---------------- Kernel A: u_k and Gram, shuffle-parallel -----------------
__global__ void prep_kernel(const float* __restrict__ v,
                            const float* __restrict__ m) {
    int tid = threadIdx.x;            // 1024 threads, tid == d
    int wid = tid >> 5, lane = tid & 31;
    float val[KK], ss[KK];
#pragma unroll
    for (int k = 0; k < KK; k++) {
        float mv = m[k * DD + tid];
        float sig = 1.0f / (1.0f + expf(-mv));
        val[k] = v[k * DD + tid] * sig;
        ss[k] = val[k] * val[k];
    }
#pragma unroll
    for (int off = 16; off; off >>= 1)
#pragma unroll
        for (int k = 0; k < KK; k++)
            ss[k] += __shfl_xor_sync(0xFFFFFFFFu, ss[k], off);

    __shared__ float sred[32][KK];
    __shared__ float sinv[KK];
    if (lane == 0)
#pragma unroll
        for (int k = 0; k < KK; k++) sred[wid][k] = ss[k];
    __syncthreads();
    if (tid < 32) {
        float t[KK];
#pragma unroll
        for (int k = 0; k < KK; k++) t[k] = sred[tid][k];
#pragma unroll
        for (int off = 16; off; off >>= 1)
#pragma unroll
            for (int k = 0; k < KK; k++)
                t[k] += __shfl_xor_sync(0xFFFFFFFFu, t[k], off);
        if (tid == 0)
#pragma unroll
            for (int k = 0; k < KK; k++) sinv[k] = 1.0f / (sqrtf(t[k]) + EPSV);
    }
    __syncthreads();
    float un[KK];
#pragma unroll
    for (int k = 0; k < KK; k++) {
        un[k] = val[k] * sinv[k];
        g_u[k * DD + tid] = un[k];
    }
    // Gram: 6 upper-triangle pairs in parallel
    float pp[6] = {un[0]*un[1], un[0]*un[2], un[0]*un[3],
                   un[1]*un[2], un[1]*un[3], un[2]*un[3]};
#pragma unroll
    for (int off = 16; off; off >>= 1)
#pragma unroll
        for (int p = 0; p < 6; p++)
            pp[p] += __shfl_xor_sync(0xFFFFFFFFu, pp[p], off);
    __shared__ float sred6[32][6];
    if (lane == 0)
#pragma unroll
        for (int p = 0; p < 6; p++) sred6[wid][p] = pp[p];
    __syncthreads();
    if (tid < 32) {
        float t[6];
#pragma unroll
        for (int p = 0; p < 6; p++) t[p] = sred6[tid][p];
#pragma unroll
        for (int off = 16; off; off >>= 1)
#pragma unroll
            for (int p = 0; p < 6; p++)
                t[p] += __shfl_xor_sync(0xFFFFFFFFu, t[p], off);
        if (tid == 0) {
            g_gram[0 * KK + 1] = t[0];
            g_gram[0 * KK + 2] = t[1];
            g_gram[0 * KK + 3] = t[2];
            g_gram[1 * KK + 2] = t[3];
            g_gram[1 * KK + 3] = t[4];
            g_gram[2 * KK + 3] = t[5];
        }
    }
}

// ---------------- Fused kernel: w projection + coefficient pass ------------
// Blocks [0, W_BLOCKS):          w_k[c] = cls_W[k,c,:] . u_k
// Blocks [W_BLOCKS, +C_BLOCKS):  one pass over E -> c_k (4 tokens/warp)
// Streaming loads (__ldcs) on E and W: read-once data, keep L2 for g_C.
__global__ void __launch_bounds__(256)
fused_kernel(const float* __restrict__ E,
             const float* __restrict__ W,
             const float* __restrict__ beta) {
    __shared__ float su[KK * DD];    // 16 KB: the 4 u vectors (coeff part)
    __shared__ float sg[KK * KK];
    __shared__ float sb[KK];

    int tid = threadIdx.x;           // 256
    int wid = tid >> 5, lane = tid & 31;

    if (blockIdx.x < W_BLOCKS) {
        // ---- w part: one block per (k, c) ----
        int bx = blockIdx.x;
        int k = bx / CCLS;
        int c = bx - k * CCLS;
        const float4* wr = (const float4*)(W + ((size_t)k * CCLS + c) * DD);
        const float4* u4g = (const float4*)(g_u + k * DD);
        float4 w = __ldcs(wr + tid);
        float4 u = u4g[tid];
        float acc = w.x * u.x + w.y * u.y + w.z * u.z + w.w * u.w;
#pragma unroll
        for (int off = 16; off; off >>= 1)
            acc += __shfl_xor_sync(0xFFFFFFFFu, acc, off);
        __shared__ float sd[8];
        if (lane == 0) sd[wid] = acc;
        __syncthreads();
        if (tid == 0) {
            float s = sd[0];
#pragma unroll
            for (int i = 1; i < 8; i++) s += sd[i];
            g_w[k * CCLS + c] = s;
        }
        return;
    }

    // ---- coeff part: warp handles 4 tokens ----
    int cb = blockIdx.x - W_BLOCKS;
    for (int i = tid; i < KK * DD; i += 256) su[i] = g_u[i];
    if (tid < KK * KK) sg[tid] = g_gram[tid];
    if (tid < KK) sb[tid] = beta[tid];
    __syncthreads();

    int tok0 = cb * 32 + wid * 4;   // 4 tokens per warp
    const float4* u4 = (const float4*)su;
    const float4* e4 = (const float4*)(E + (size_t)tok0 * DD);

    float acc[4][KK];
#pragma unroll
    for (int j = 0; j < 4; j++)
#pragma unroll
        for (int k = 0; k < KK; k++) acc[j][k] = 0.f;

#pragma unroll
    for (int i = 0; i < 8; i++) {
        int idx = i * 32 + lane;
        float4 ua = u4[idx];
        float4 ub = u4[256 + idx];
        float4 uc = u4[512 + idx];
        float4 ud = u4[768 + idx];
#pragma unroll
        for (int j = 0; j < 4; j++) {
            float4 e = __ldcs(e4 + (size_t)j * 256 + idx);
            acc[j][0] += e.x*ua.x + e.y*ua.y + e.z*ua.z + e.w*ua.w;
            acc[j][1] += e.x*ub.x + e.y*ub.y + e.z*ub.z + e.w*ub.w;
            acc[j][2] += e.x*uc.x + e.y*uc.y + e.z*uc.z + e.w*uc.w;
            acc[j][3] += e.x*ud.x + e.y*ud.y + e.z*ud.z + e.w*ud.w;
        }
    }
#pragma unroll
    for (int off = 16; off; off >>= 1)
#pragma unroll
        for (int j = 0; j < 4; j++)
#pragma unroll
            for (int k = 0; k < KK; k++)
                acc[j][k] += __shfl_down_sync(0xFFFFFFFFu, acc[j][k], off);

    if (lane == 0) {
#pragma unroll
        for (int j = 0; j < 4; j++) {
            int token = tok0 + j;
            float c0 = acc[j][0];
            float c1 = acc[j][1] - sb[0]*c0*sg[0*KK+1];
            float c2 = acc[j][2] - sb[0]*c0*sg[0*KK+2] - sb[1]*c1*sg[1*KK+2];
            float c3 = acc[j][3] - sb[0]*c0*sg[0*KK+3] - sb[1]*c1*sg[1*KK+3]
                                 - sb[2]*c2*sg[2*KK+3];
            g_C[0 * BB * TT + token] = c0;
            g_C[1 * BB * TT + token] = c1;
            g_C[2 * BB * TT + token] = c2;
            g_C[3 * BB * TT + token] = c3;
        }
    }
}

// ---------------- Kernel D: stats per (b,k) + fused output -----------------
// 512 threads; row in registers; warp-local top-8 then single-warp merge.
// The LAST finishing block also computes out[b,c] (fused, saves a launch),
// then resets the counter so graph replays stay deterministic.
__global__ void stats_kernel(const float* __restrict__ clsb,
                             const float* __restrict__ alpha,
                             float* __restrict__ out) {
    int b = blockIdx.x;
    int k = blockIdx.y;
    int tid = threadIdx.x;           // 512
    int wid = tid >> 5, lane = tid & 31;
    const float4* src = (const float4*)(g_C + ((size_t)k * BB + b) * TT);
    float4 p = src[tid];
    float4 q = src[tid + 512];
    float r[8] = {p.x, p.y, p.z, p.w, q.x, q.y, q.z, q.w};

    __shared__ float smax[16];
    __shared__ float sse[16];
    __shared__ float ssce[16];
    __shared__ float cand[16 * TOPM];   // per-warp top-8 candidates
    __shared__ int s_last;

    // block max (one barrier)
    float mx = r[0];
#pragma unroll
    for (int s = 1; s < 8; s++) mx = fmaxf(mx, r[s]);
#pragma unroll
    for (int off = 16; off; off >>= 1)
        mx = fmaxf(mx, __shfl_xor_sync(0xFFFFFFFFu, mx, off));
    if (lane == 0) smax[wid] = mx;
    __syncthreads();
    mx = smax[0];
#pragma unroll
    for (int w = 1; w < 16; w++) mx = fmaxf(mx, smax[w]);

    // exp sums (warp partials -> smem; merged by warp 0 later)
    float se = 0.f, sce = 0.f;
#pragma unroll
    for (int s = 0; s < 8; s++) {
        float e = __expf((r[s] - mx) * TEMPR);
        se += e;
        sce += r[s] * e;
    }
#pragma unroll
    for (int off = 16; off; off >>= 1) {
        se  += __shfl_xor_sync(0xFFFFFFFFu, se, off);
        sce += __shfl_xor_sync(0xFFFFFFFFu, sce, off);
    }
    if (lane == 0) { sse[wid] = se; ssce[wid] = sce; }

    // warp-local top-8 (no barriers): 8 rounds of warp argmax with exclusion
    unsigned excl = 0;
#pragma unroll
    for (int rr = 0; rr < TOPM; rr++) {
        float lm = -INFINITY;
        int ls = 0;
#pragma unroll
        for (int s = 0; s < 8; s++) {
            bool ok = !((excl >> s) & 1u);
            if (ok && r[s] > lm) { lm = r[s]; ls = s; }
        }
        int li = (lane << 3) | ls;
#pragma unroll
        for (int off = 16; off; off >>= 1) {
            float ov = __shfl_xor_sync(0xFFFFFFFFu, lm, off);
            int   oi = __shfl_xor_sync(0xFFFFFFFFu, li, off);
            if (ov > lm) { lm = ov; li = oi; }
        }
        if (lane == 0) cand[wid * TOPM + rr] = lm;
        if ((li >> 3) == lane) excl |= 1u << (li & 7);
    }
    __syncthreads();

    // warp 0 merges 128 candidates -> block top-8 and writes result
    if (wid == 0) {
        float c4[4];
#pragma unroll
        for (int i = 0; i < 4; i++) c4[i] = cand[lane * 4 + i];
        unsigned ex2 = 0;
        float hard = 0.f;
#pragma unroll
        for (int rr = 0; rr < TOPM; rr++) {
            float lm = -INFINITY;
            int ls = 0;
#pragma unroll
            for (int s = 0; s < 4; s++) {
                bool ok = !((ex2 >> s) & 1u);
                if (ok && c4[s] > lm) { lm = c4[s]; ls = s; }
            }
            int li = (lane << 2) | ls;
#pragma unroll
            for (int off = 16; off; off >>= 1) {
                float ov = __shfl_xor_sync(0xFFFFFFFFu, lm, off);
                int   oi = __shfl_xor_sync(0xFFFFFFFFu, li, off);
                if (ov > lm) { lm = ov; li = oi; }
            }
            hard += lm;
            if ((li >> 2) == lane) ex2 |= 1u << (li & 3);
        }
        if (lane == 0) {
            float se_t = 0.f, sce_t = 0.f;
#pragma unroll
            for (int w = 0; w < 16; w++) { se_t += sse[w]; sce_t += ssce[w]; }
            g_s[b * KK + k] = 0.5f * (hard + sce_t / se_t);
            __threadfence();
            int prev = atomicAdd(&g_cnt, 1);
            s_last = (prev == BB * KK - 1) ? 1 : 0;
        }
    }
    __syncthreads();

    // last block computes the output (all g_s now visible)
    if (s_last) {
        __threadfence();
        __shared__ float sal[KK], ssv[BB * KK];
        if (tid < KK) sal[tid] = alpha[tid];
        if (tid < BB * KK) ssv[tid] = g_s[tid];
        __syncthreads();
        for (int i = tid; i < BB * CCLS; i += 512) {
            int bb = i / CCLS;
            int c = i - bb * CCLS;
            float acc2 = 0.f;
#pragma unroll
            for (int kk2 = 0; kk2 < KK; kk2++) {
                acc2 += sal[kk2] * (ssv[bb * KK + kk2] * g_w[kk2 * CCLS + c]
                                    + clsb[kk2 * CCLS + c]);
            }
            out[i] = acc2;
        }
        // reset counter for deterministic graph replays
        if (tid == 0) g_cnt = 0;
    }
}

extern "C" void kernel_launch(void* const* d_in, const int* in_sizes, int n_in,
                              void* d_out, int out_size) {
    const float* E      = (const float*)d_in[0];  // (B,T,D)
    const float* v      = (const float*)d_in[1];  // (K,D)
    const float* mlog   = (const float*)d_in[2];  // (K,D)
    const float* clsW   = (const float*)d_in[3];  // (K,C,D)
    const float* clsb   = (const float*)d_in[4];  // (K,C)
    const float* beta   = (const float*)d_in[5];  // (K,)
    const float* alpha  = (const float*)d_in[6];  // (K,)
    float* out = (float*)d_out;                   // (B,C)

    prep_kernel<<<1, 1024>>>(v, mlog);
    fused_kernel<<<W_BLOCKS + C_BLOCKS, 256>>>(E, clsW, beta);
    dim3 sg(BB, KK);
    stats_kernel<<<sg, 512>>>(clsb, alpha, out);
}

// round 8
// speedup vs baseline: 1.3617x; 1.2316x over previous
#include <cuda_runtime.h>
#include <math.h>

#define BB 16
#define TT 4096
#define DD 1024
#define CCLS 1000
#define KK 4
#define TOPM 8
#define TEMPR (1.0f/0.07f)
#define EPSV 1e-6f

#define W_BLOCKS ((CCLS * KK) / 8)     // 500: 8 warps/block, warp-per-class
#define C_BLOCKS ((BB * TT) / 32)      // 2048 (4 tokens per warp, 8 warps)

// scratch (allocation-free rule: __device__ globals)
__device__ float g_u[KK * DD];       // unit peel directions
__device__ float g_gram[KK * KK];    // u_j . u_k (only j<k entries used)
__device__ float g_w[KK * CCLS];     // W_k @ u_k
__device__ float g_C[KK * BB * TT];  // coefficient fields c_k[b,t]
__device__ float g_s[BB * KK];       // 0.5*(hard+soft) scalars

// ---------------- Kernel A: u_k and Gram, shuffle-parallel -----------------
__global__ void prep_kernel(const float* __restrict__ v,
                            const float* __restrict__ m) {
    int tid = threadIdx.x;            // 1024 threads, tid == d
    int wid = tid >> 5, lane = tid & 31;
    float val[KK], ss[KK];
#pragma unroll
    for (int k = 0; k < KK; k++) {
        float mv = m[k * DD + tid];
        float sig = 1.0f / (1.0f + expf(-mv));
        val[k] = v[k * DD + tid] * sig;
        ss[k] = val[k] * val[k];
    }
#pragma unroll
    for (int off = 16; off; off >>= 1)
#pragma unroll
        for (int k = 0; k < KK; k++)
            ss[k] += __shfl_xor_sync(0xFFFFFFFFu, ss[k], off);

    __shared__ float sred[32][KK];
    __shared__ float sinv[KK];
    if (lane == 0)
#pragma unroll
        for (int k = 0; k < KK; k++) sred[wid][k] = ss[k];
    __syncthreads();
    if (tid < 32) {
        float t[KK];
#pragma unroll
        for (int k = 0; k < KK; k++) t[k] = sred[tid][k];
#pragma unroll
        for (int off = 16; off; off >>= 1)
#pragma unroll
            for (int k = 0; k < KK; k++)
                t[k] += __shfl_xor_sync(0xFFFFFFFFu, t[k], off);
        if (tid == 0)
#pragma unroll
            for (int k = 0; k < KK; k++) sinv[k] = 1.0f / (sqrtf(t[k]) + EPSV);
    }
    __syncthreads();
    float un[KK];
#pragma unroll
    for (int k = 0; k < KK; k++) {
        un[k] = val[k] * sinv[k];
        g_u[k * DD + tid] = un[k];
    }
    // Gram: 6 upper-triangle pairs in parallel
    float pp[6] = {un[0]*un[1], un[0]*un[2], un[0]*un[3],
                   un[1]*un[2], un[1]*un[3], un[2]*un[3]};
#pragma unroll
    for (int off = 16; off; off >>= 1)
#pragma unroll
        for (int p = 0; p < 6; p++)
            pp[p] += __shfl_xor_sync(0xFFFFFFFFu, pp[p], off);
    __shared__ float sred6[32][6];
    if (lane == 0)
#pragma unroll
        for (int p = 0; p < 6; p++) sred6[wid][p] = pp[p];
    __syncthreads();
    if (tid < 32) {
        float t[6];
#pragma unroll
        for (int p = 0; p < 6; p++) t[p] = sred6[tid][p];
#pragma unroll
        for (int off = 16; off; off >>= 1)
#pragma unroll
            for (int p = 0; p < 6; p++)
                t[p] += __shfl_xor_sync(0xFFFFFFFFu, t[p], off);
        if (tid == 0) {
            g_gram[0 * KK + 1] = t[0];
            g_gram[0 * KK + 2] = t[1];
            g_gram[0 * KK + 3] = t[2];
            g_gram[1 * KK + 2] = t[3];
            g_gram[1 * KK + 3] = t[4];
            g_gram[2 * KK + 3] = t[5];
        }
    }
}

// ---------------- Fused kernel: w projection + coefficient pass ------------
// Blocks [0, W_BLOCKS):   warp-per-class w_k[c] = cls_W[k,c,:] . u_k
//                         (MLP=8/lane, warp-shuffle only, no barriers)
// Blocks [W_BLOCKS, ...): one pass over E -> c_k (4 tokens/warp)
__global__ void fused_kernel(const float* __restrict__ E,
                             const float* __restrict__ W,
                             const float* __restrict__ beta) {
    __shared__ float su[KK * DD];    // 16 KB: the 4 u vectors (coeff part)
    __shared__ float sg[KK * KK];
    __shared__ float sb[KK];

    int tid = threadIdx.x;           // 256
    int wid = tid >> 5, lane = tid & 31;

    if (blockIdx.x < W_BLOCKS) {
        // ---- w part: one warp per (k, c) row ----
        int gw = blockIdx.x * 8 + wid;      // [0, 4000)
        int k = gw / CCLS;
        int c = gw - k * CCLS;
        const float4* wr = (const float4*)(W + ((size_t)k * CCLS + c) * DD);
        const float4* u4g = (const float4*)(g_u + k * DD);
        float acc = 0.f;
#pragma unroll
        for (int i = 0; i < 8; i++) {
            float4 w = wr[i * 32 + lane];
            float4 u = u4g[i * 32 + lane];
            acc += w.x * u.x + w.y * u.y + w.z * u.z + w.w * u.w;
        }
#pragma unroll
        for (int off = 16; off; off >>= 1)
            acc += __shfl_xor_sync(0xFFFFFFFFu, acc, off);
        if (lane == 0) g_w[k * CCLS + c] = acc;
        return;
    }

    // ---- coeff part: warp handles 4 tokens ----
    int cb = blockIdx.x - W_BLOCKS;
    for (int i = tid; i < KK * DD; i += 256) su[i] = g_u[i];
    if (tid < KK * KK) sg[tid] = g_gram[tid];
    if (tid < KK) sb[tid] = beta[tid];
    __syncthreads();

    int tok0 = cb * 32 + wid * 4;   // 4 tokens per warp
    const float4* u4 = (const float4*)su;
    const float4* e4 = (const float4*)(E + (size_t)tok0 * DD);

    float acc[4][KK];
#pragma unroll
    for (int j = 0; j < 4; j++)
#pragma unroll
        for (int k = 0; k < KK; k++) acc[j][k] = 0.f;

#pragma unroll
    for (int i = 0; i < 8; i++) {
        int idx = i * 32 + lane;
        float4 ua = u4[idx];
        float4 ub = u4[256 + idx];
        float4 uc = u4[512 + idx];
        float4 ud = u4[768 + idx];
#pragma unroll
        for (int j = 0; j < 4; j++) {
            float4 e = e4[j * 256 + idx];
            acc[j][0] += e.x*ua.x + e.y*ua.y + e.z*ua.z + e.w*ua.w;
            acc[j][1] += e.x*ub.x + e.y*ub.y + e.z*ub.z + e.w*ub.w;
            acc[j][2] += e.x*uc.x + e.y*uc.y + e.z*uc.z + e.w*uc.w;
            acc[j][3] += e.x*ud.x + e.y*ud.y + e.z*ud.z + e.w*ud.w;
        }
    }
#pragma unroll
    for (int off = 16; off; off >>= 1)
#pragma unroll
        for (int j = 0; j < 4; j++)
#pragma unroll
            for (int k = 0; k < KK; k++)
                acc[j][k] += __shfl_down_sync(0xFFFFFFFFu, acc[j][k], off);

    if (lane == 0) {
#pragma unroll
        for (int j = 0; j < 4; j++) {
            int token = tok0 + j;
            float c0 = acc[j][0];
            float c1 = acc[j][1] - sb[0]*c0*sg[0*KK+1];
            float c2 = acc[j][2] - sb[0]*c0*sg[0*KK+2] - sb[1]*c1*sg[1*KK+2];
            float c3 = acc[j][3] - sb[0]*c0*sg[0*KK+3] - sb[1]*c1*sg[1*KK+3]
                                 - sb[2]*c2*sg[2*KK+3];
            g_C[0 * BB * TT + token] = c0;
            g_C[1 * BB * TT + token] = c1;
            g_C[2 * BB * TT + token] = c2;
            g_C[3 * BB * TT + token] = c3;
        }
    }
}

// ---------------- Kernel D: per (b,k) softmax stats + top-8 sum ------------
// 512 threads; row in registers; warp-local top-8 then single-warp merge.
__global__ void stats_kernel() {
    int b = blockIdx.x;
    int k = blockIdx.y;
    int tid = threadIdx.x;           // 512
    int wid = tid >> 5, lane = tid & 31;
    const float4* src = (const float4*)(g_C + ((size_t)k * BB + b) * TT);
    float4 p = src[tid];
    float4 q = src[tid + 512];
    float r[8] = {p.x, p.y, p.z, p.w, q.x, q.y, q.z, q.w};

    __shared__ float smax[16];
    __shared__ float sse[16];
    __shared__ float ssce[16];
    __shared__ float cand[16 * TOPM];   // per-warp top-8 candidates

    // block max (one barrier)
    float mx = r[0];
#pragma unroll
    for (int s = 1; s < 8; s++) mx = fmaxf(mx, r[s]);
#pragma unroll
    for (int off = 16; off; off >>= 1)
        mx = fmaxf(mx, __shfl_xor_sync(0xFFFFFFFFu, mx, off));
    if (lane == 0) smax[wid] = mx;
    __syncthreads();
    mx = smax[0];
#pragma unroll
    for (int w = 1; w < 16; w++) mx = fmaxf(mx, smax[w]);

    // exp sums (warp partials -> smem; merged by warp 0 later)
    float se = 0.f, sce = 0.f;
#pragma unroll
    for (int s = 0; s < 8; s++) {
        float e = __expf((r[s] - mx) * TEMPR);
        se += e;
        sce += r[s] * e;
    }
#pragma unroll
    for (int off = 16; off; off >>= 1) {
        se  += __shfl_xor_sync(0xFFFFFFFFu, se, off);
        sce += __shfl_xor_sync(0xFFFFFFFFu, sce, off);
    }
    if (lane == 0) { sse[wid] = se; ssce[wid] = sce; }

    // warp-local top-8 (no barriers): 8 rounds of warp argmax with exclusion
    unsigned excl = 0;
#pragma unroll
    for (int rr = 0; rr < TOPM; rr++) {
        float lm = -INFINITY;
        int ls = 0;
#pragma unroll
        for (int s = 0; s < 8; s++) {
            bool ok = !((excl >> s) & 1u);
            if (ok && r[s] > lm) { lm = r[s]; ls = s; }
        }
        int li = (lane << 3) | ls;
#pragma unroll
        for (int off = 16; off; off >>= 1) {
            float ov = __shfl_xor_sync(0xFFFFFFFFu, lm, off);
            int   oi = __shfl_xor_sync(0xFFFFFFFFu, li, off);
            if (ov > lm) { lm = ov; li = oi; }
        }
        if (lane == 0) cand[wid * TOPM + rr] = lm;
        if ((li >> 3) == lane) excl |= 1u << (li & 7);
    }
    __syncthreads();

    // warp 0 merges 128 candidates -> block top-8 and writes result
    if (wid == 0) {
        float c4[4];
#pragma unroll
        for (int i = 0; i < 4; i++) c4[i] = cand[lane * 4 + i];
        unsigned ex2 = 0;
        float hard = 0.f;
#pragma unroll
        for (int rr = 0; rr < TOPM; rr++) {
            float lm = -INFINITY;
            int ls = 0;
#pragma unroll
            for (int s = 0; s < 4; s++) {
                bool ok = !((ex2 >> s) & 1u);
                if (ok && c4[s] > lm) { lm = c4[s]; ls = s; }
            }
            int li = (lane << 2) | ls;
#pragma unroll
            for (int off = 16; off; off >>= 1) {
                float ov = __shfl_xor_sync(0xFFFFFFFFu, lm, off);
                int   oi = __shfl_xor_sync(0xFFFFFFFFu, li, off);
                if (ov > lm) { lm = ov; li = oi; }
            }
            hard += lm;
            if ((li >> 2) == lane) ex2 |= 1u << (li & 3);
        }
        if (lane == 0) {
            float se_t = 0.f, sce_t = 0.f;
#pragma unroll
            for (int w = 0; w < 16; w++) { se_t += sse[w]; sce_t += ssce[w]; }
            g_s[b * KK + k] = 0.5f * (hard + sce_t / se_t);
        }
    }
}

// ---------------- Kernel E: out[b,c] = sum_k alpha_k (s w_k[c] + b_k[c]) ---
__global__ void out_kernel(const float* __restrict__ clsb,
                           const float* __restrict__ alpha,
                           float* __restrict__ out) {
    int i = blockIdx.x * 256 + threadIdx.x;
    if (i >= BB * CCLS) return;
    int b = i / CCLS;
    int c = i - b * CCLS;
    float acc = 0.f;
#pragma unroll
    for (int k = 0; k < KK; k++) {
        acc += alpha[k] * (g_s[b * KK + k] * g_w[k * CCLS + c] + clsb[k * CCLS + c]);
    }
    out[i] = acc;
}

extern "C" void kernel_launch(void* const* d_in, const int* in_sizes, int n_in,
                              void* d_out, int out_size) {
    const float* E      = (const float*)d_in[0];  // (B,T,D)
    const float* v      = (const float*)d_in[1];  // (K,D)
    const float* mlog   = (const float*)d_in[2];  // (K,D)
    const float* clsW   = (const float*)d_in[3];  // (K,C,D)
    const float* clsb   = (const float*)d_in[4];  // (K,C)
    const float* beta   = (const float*)d_in[5];  // (K,)
    const float* alpha  = (const float*)d_in[6];  // (K,)
    float* out = (float*)d_out;                   // (B,C)

    prep_kernel<<<1, 1024>>>(v, mlog);
    fused_kernel<<<W_BLOCKS + C_BLOCKS, 256>>>(E, clsW, beta);
    dim3 sg(BB, KK);
    stats_kernel<<<sg, 512>>>();
    out_kernel<<<(BB * CCLS + 255) / 256, 256>>>(clsb, alpha, out);
}